// round 1
// baseline (speedup 1.0000x reference)
#include <cuda_runtime.h>

// LocalFeatureAggregation on GB300 — fp32 baseline, algebraically folded.
//
// Pipeline (after folding BN affine into the weights):
//   1) x = relu(F @ W1 + b1)                          (50000 x 256)
//   2) per point n: L = x[idx[n]] @ Ws'   (16 x 256)  logits; BN-const term
//      cancels in softmax (softmax is over k per channel).
//      s = softmax_k(L);  p[n] = sum_k s .* x[idx[n]]
//   3) out = p @ Wm' + bm'   where Wm' = diag(a) Wm, bm' = c@Wm + bm,
//      a = gamma*rsqrt(var+eps), c = beta - mean*a  (uses softmax colsum==1)

#define N_PTS 50000
#define KNB   16
#define C_IN  128
#define C2    256
#define C_OUT 128
#define NK    (N_PTS * KNB)

// Scratch (allocation-free rule: __device__ globals)
__device__ float g_x[(size_t)N_PTS * C2];     // relu(F@W1+b1)
__device__ float g_P[(size_t)N_PTS * C2];     // pooled features (pre final GEMM)
__device__ float g_WsP[C2 * C2];              // diag(a) @ Ws
__device__ float g_WmP[C2 * C_OUT];           // diag(a) @ Wm
__device__ float g_bmP[C_OUT];                // c@Wm + bm
__device__ float g_avec[C2];
__device__ float g_cvec[C2];
__device__ int   g_rows[NK];                  // neighbor indices as int32
__device__ int   g_is64;

// ---------------------------------------------------------------------------
// prep: BN folding + index dtype detection
// ---------------------------------------------------------------------------
__global__ __launch_bounds__(256) void prep_kernel(
    const float* __restrict__ gamma, const float* __restrict__ beta,
    const float* __restrict__ rmean, const float* __restrict__ rvar,
    const float* __restrict__ Ws,    const float* __restrict__ Wm,
    const float* __restrict__ bm,    const void* __restrict__ nidx_raw)
{
    int t = threadIdx.x;
    float a = gamma[t] * rsqrtf(rvar[t] + 1e-5f);
    float c = beta[t] - rmean[t] * a;
    g_avec[t] = a;
    g_cvec[t] = c;
    if (t == 0) {
        // Detect int64 vs int32 index buffer: values < 50000, so if int64,
        // every odd 32-bit word (high half, little-endian) is zero.
        const int* ii = (const int*)nidx_raw;
        int is64 = 1;
        for (int i = 1; i < 2048; i += 2) {
            if (ii[i] != 0) { is64 = 0; break; }
        }
        g_is64 = is64;
    }
    __syncthreads();
    for (int i = t; i < C2 * C2; i += 256)
        g_WsP[i] = g_avec[i >> 8] * Ws[i];
    for (int i = t; i < C2 * C_OUT; i += 256)
        g_WmP[i] = g_avec[i / C_OUT] * Wm[i];
    if (t < C_OUT) {
        float s = bm[t];
        for (int j = 0; j < C2; j++)
            s += g_cvec[j] * Wm[j * C_OUT + t];
        g_bmP[t] = s;
    }
}

__global__ __launch_bounds__(256) void idx_kernel(const void* __restrict__ nidx_raw)
{
    int i = blockIdx.x * 256 + threadIdx.x;
    if (i >= NK) return;
    if (g_is64) g_rows[i] = (int)((const long long*)nidx_raw)[i];
    else        g_rows[i] = ((const int*)nidx_raw)[i];
}

// ---------------------------------------------------------------------------
// Generic guarded SGEMM: C = [relu](A @ B + bias), BM=BN=64, BK=16, 256 thr
// MODE 0: A=features, B=W1, bias=b1, C=g_x, relu.   MODE 1: A=g_P, B=g_WmP,
// bias=g_bmP, C=out.
// ---------------------------------------------------------------------------
template<int MODE>
__global__ __launch_bounds__(256) void gemm64_kernel(
    const float* __restrict__ Ain, const float* __restrict__ Bin,
    const float* __restrict__ biasin, float* __restrict__ Cout,
    int M, int N, int K)
{
    const float* A    = (MODE == 0) ? Ain    : g_P;
    const float* B    = (MODE == 0) ? Bin    : g_WmP;
    const float* bias = (MODE == 0) ? biasin : g_bmP;
    float*       C    = (MODE == 0) ? g_x    : Cout;

    __shared__ float AsT[16][68];
    __shared__ float Bs[16][64];

    int t  = threadIdx.x;
    int tx = t & 15, ty = t >> 4;
    int rowBase = blockIdx.x * 64;
    int colBase = blockIdx.y * 64;

    int lr = t >> 2, lk = (t & 3) << 2;        // A loader: row lr, 4 cols at lk
    int grow = rowBase + lr;
    bool rok = grow < M;
    const float* aptr = A + (size_t)grow * K + lk;
    int bkk = t >> 4, bc = (t & 15) << 2;      // B loader
    const float* bptr = B + (size_t)bkk * N + colBase + bc;

    float acc[4][4] = {};

    for (int kb = 0; kb < K; kb += 16) {
        float4 av = make_float4(0.f, 0.f, 0.f, 0.f);
        if (rok) av = *(const float4*)(aptr + kb);
        AsT[lk + 0][lr] = av.x; AsT[lk + 1][lr] = av.y;
        AsT[lk + 2][lr] = av.z; AsT[lk + 3][lr] = av.w;
        float4 bv = *(const float4*)(bptr + (size_t)kb * N);
        *(float4*)&Bs[bkk][bc] = bv;
        __syncthreads();
#pragma unroll
        for (int kk = 0; kk < 16; kk++) {
            float4 a = *(float4*)&AsT[kk][ty << 2];
            float4 b = *(float4*)&Bs[kk][tx << 2];
            acc[0][0] += a.x * b.x; acc[0][1] += a.x * b.y; acc[0][2] += a.x * b.z; acc[0][3] += a.x * b.w;
            acc[1][0] += a.y * b.x; acc[1][1] += a.y * b.y; acc[1][2] += a.y * b.z; acc[1][3] += a.y * b.w;
            acc[2][0] += a.z * b.x; acc[2][1] += a.z * b.y; acc[2][2] += a.z * b.z; acc[2][3] += a.z * b.w;
            acc[3][0] += a.w * b.x; acc[3][1] += a.w * b.y; acc[3][2] += a.w * b.z; acc[3][3] += a.w * b.w;
        }
        __syncthreads();
    }

    float4 b4 = *(const float4*)(bias + colBase + (tx << 2));
#pragma unroll
    for (int i = 0; i < 4; i++) {
        int r = rowBase + (ty << 2) + i;
        if (r < M) {
            float4 o;
            o.x = acc[i][0] + b4.x; o.y = acc[i][1] + b4.y;
            o.z = acc[i][2] + b4.z; o.w = acc[i][3] + b4.w;
            if (MODE == 0) {
                o.x = fmaxf(o.x, 0.f); o.y = fmaxf(o.y, 0.f);
                o.z = fmaxf(o.z, 0.f); o.w = fmaxf(o.w, 0.f);
            }
            *(float4*)(C + (size_t)r * N + colBase + (tx << 2)) = o;
        }
    }
}

// ---------------------------------------------------------------------------
// Fused attention: per block = 8 points x 128-channel slice.
//   GEMM: logits(128 rows x 128 cols) = gather(x)[128 x 256] @ WsP[:, slice]
//   then per (point, channel) softmax over k=16 and weighted sum of x.
// Dynamic smem: 128 ints (rowptr) + 16896 floats (GEMM bufs / logits union)
// ---------------------------------------------------------------------------
#define ATTN_SMEM_BYTES ((128 + 16896) * 4)

__global__ __launch_bounds__(256) void attn_kernel()
{
    extern __shared__ float smem[];
    int*   rowptr = (int*)smem;
    float* buf    = smem + 128;          // AsT: [16][132] -> 2112 floats
    float* Bsm    = buf + 16 * 132;      // Bs:  [16][128] -> 2048 floats
    float* Ls     = buf;                 // logits [128][132] (reuses GEMM bufs)

    int t  = threadIdx.x;
    int tx = t & 15, ty = t >> 4;
    int pbase = blockIdx.x * 8;          // 8 points per block
    int cbase = blockIdx.y * 128;        // channel slice

    if (t < 128) rowptr[t] = g_rows[pbase * KNB + t];   // t = pi*16 + k
    __syncthreads();

    int ar = t >> 1, ap = (t & 1) << 3;  // A loader: row ar, 8 cols at ap
    const float* abase = g_x + (size_t)rowptr[ar] * C2 + ap;
    const float* bbase = g_WsP + (size_t)ty * C2 + cbase + (tx << 3);

    float acc[8][8] = {};

    for (int kb = 0; kb < C2; kb += 16) {
        float4 a0 = *(const float4*)(abase + kb);
        float4 a1 = *(const float4*)(abase + kb + 4);
        buf[(ap + 0) * 132 + ar] = a0.x; buf[(ap + 1) * 132 + ar] = a0.y;
        buf[(ap + 2) * 132 + ar] = a0.z; buf[(ap + 3) * 132 + ar] = a0.w;
        buf[(ap + 4) * 132 + ar] = a1.x; buf[(ap + 5) * 132 + ar] = a1.y;
        buf[(ap + 6) * 132 + ar] = a1.z; buf[(ap + 7) * 132 + ar] = a1.w;
        float4 b0 = *(const float4*)(bbase + (size_t)kb * C2);
        float4 b1 = *(const float4*)(bbase + (size_t)kb * C2 + 4);
        *(float4*)&Bsm[ty * 128 + (tx << 3)]     = b0;
        *(float4*)&Bsm[ty * 128 + (tx << 3) + 4] = b1;
        __syncthreads();
#pragma unroll
        for (int kk = 0; kk < 16; kk++) {
            float4 aA = *(float4*)&buf[kk * 132 + (ty << 2)];
            float4 aB = *(float4*)&buf[kk * 132 + 64 + (ty << 2)];
            float4 bA = *(float4*)&Bsm[kk * 128 + (tx << 2)];
            float4 bB = *(float4*)&Bsm[kk * 128 + 64 + (tx << 2)];
            float av[8] = {aA.x, aA.y, aA.z, aA.w, aB.x, aB.y, aB.z, aB.w};
            float bv[8] = {bA.x, bA.y, bA.z, bA.w, bB.x, bB.y, bB.z, bB.w};
#pragma unroll
            for (int i = 0; i < 8; i++)
#pragma unroll
                for (int j = 0; j < 8; j++)
                    acc[i][j] += av[i] * bv[j];
        }
        __syncthreads();
    }

    // Spill logits to smem (pitch 132 to dodge bank conflicts on column reads)
#pragma unroll
    for (int ih = 0; ih < 2; ih++)
#pragma unroll
        for (int i = 0; i < 4; i++) {
            int r = ih * 64 + (ty << 2) + i;
#pragma unroll
            for (int jh = 0; jh < 2; jh++) {
                float4 o = make_float4(acc[ih * 4 + i][jh * 4 + 0],
                                       acc[ih * 4 + i][jh * 4 + 1],
                                       acc[ih * 4 + i][jh * 4 + 2],
                                       acc[ih * 4 + i][jh * 4 + 3]);
                *(float4*)&Ls[r * 132 + jh * 64 + (tx << 2)] = o;
            }
        }
    __syncthreads();

    // Softmax over k per (point, channel) + weighted pooling of x
#pragma unroll
    for (int s = 0; s < 4; s++) {
        int q  = t + (s << 8);
        int c  = q & 127;
        int pi = q >> 7;
        const float* lp = Ls + (pi * 16) * 132 + c;
        float v[16];
        float m = -1e30f;
#pragma unroll
        for (int k = 0; k < 16; k++) { v[k] = lp[k * 132]; m = fmaxf(m, v[k]); }
        float sum = 0.f;
#pragma unroll
        for (int k = 0; k < 16; k++) { v[k] = __expf(v[k] - m); sum += v[k]; }
        float inv = 1.0f / sum;
        int gcol = cbase + c;
        float p = 0.f;
#pragma unroll
        for (int k = 0; k < 16; k++)
            p += v[k] * __ldg(&g_x[(size_t)rowptr[pi * 16 + k] * C2 + gcol]);
        g_P[(size_t)(pbase + pi) * C2 + gcol] = p * inv;
    }
}

// ---------------------------------------------------------------------------
extern "C" void kernel_launch(void* const* d_in, const int* in_sizes, int n_in,
                              void* d_out, int out_size)
{
    const float* features = (const float*)d_in[0];
    const void*  nidx     = d_in[1];
    const float* W1    = (const float*)d_in[2];
    const float* b1    = (const float*)d_in[3];
    const float* gamma = (const float*)d_in[4];
    const float* beta  = (const float*)d_in[5];
    const float* rmean = (const float*)d_in[6];
    const float* rvar  = (const float*)d_in[7];
    const float* Ws    = (const float*)d_in[8];
    const float* Wm    = (const float*)d_in[9];
    const float* bm    = (const float*)d_in[10];
    float* out = (float*)d_out;

    cudaFuncSetAttribute(attn_kernel,
                         cudaFuncAttributeMaxDynamicSharedMemorySize,
                         ATTN_SMEM_BYTES);

    prep_kernel<<<1, 256>>>(gamma, beta, rmean, rvar, Ws, Wm, bm, nidx);
    idx_kernel<<<(NK + 255) / 256, 256>>>(nidx);
    gemm64_kernel<0><<<dim3((N_PTS + 63) / 64, C2 / 64), 256>>>(
        features, W1, b1, nullptr, N_PTS, C2, C_IN);
    attn_kernel<<<dim3(N_PTS / 8, 2), 256, ATTN_SMEM_BYTES>>>();
    gemm64_kernel<1><<<dim3((N_PTS + 63) / 64, C_OUT / 64), 256>>>(
        nullptr, nullptr, nullptr, out, N_PTS, C_OUT, C2);
}

// round 5
// speedup vs baseline: 4.4856x; 4.4856x over previous
#include <cuda_runtime.h>

// LocalFeatureAggregation on GB300 — gather commutes past the score GEMM.
//
//   logits[n,k,:] = (a*x[idx]+c) @ Ws = x[idx] @ (diag(a)Ws) + const(c@Ws)
//   The const term cancels in softmax over k. And x[idx]@WsP = Y[idx] where
//   Y = x @ WsP is computed ONCE (6.6 GFLOP instead of 105 GFLOP).
//
// Pipeline:
//   1) x = relu(F @ W1 + b1)            (50000 x 256)   GEMM
//   2) Y = x @ WsP                      (50000 x 256)   GEMM
//   3) pool: per (n,c): s=softmax_k(Y[idx[n,k]][c]); P[n,c]=sum_k s*x[idx][c]
//   4) out = P @ WmP + bmP              (50000 x 128)   GEMM
//   where a=gamma*rsqrt(var+eps), c=beta-mean*a, WmP=diag(a)Wm, bmP=c@Wm+bm
//   (softmax columns sum to 1 -> BN affine folds into the final GEMM).

#define N_PTS 50000
#define KNB   16
#define C_IN  128
#define C2    256
#define C_OUT 128
#define NK    (N_PTS * KNB)

__device__ float g_x[(size_t)N_PTS * C2];
__device__ float g_Y[(size_t)N_PTS * C2];
__device__ float g_P[(size_t)N_PTS * C2];
__device__ float g_WsP[C2 * C2];
__device__ float g_WmP[C2 * C_OUT];
__device__ float g_bmP[C_OUT];
__device__ float g_avec[C2];
__device__ float g_cvec[C2];
__device__ int   g_rows[NK];
__device__ int   g_is64;

// ---------------------------------------------------------------------------
// prep: BN folding + index dtype detection
// ---------------------------------------------------------------------------
__global__ __launch_bounds__(256) void prep_kernel(
    const float* __restrict__ gamma, const float* __restrict__ beta,
    const float* __restrict__ rmean, const float* __restrict__ rvar,
    const float* __restrict__ Ws,    const float* __restrict__ Wm,
    const float* __restrict__ bm,    const void* __restrict__ nidx_raw)
{
    int t = threadIdx.x;
    float a = gamma[t] * rsqrtf(rvar[t] + 1e-5f);
    float c = beta[t] - rmean[t] * a;
    g_avec[t] = a;
    g_cvec[t] = c;
    if (t == 0) {
        // int64 vs int32: values < 50000, so int64 -> odd 32-bit words all 0
        const int* ii = (const int*)nidx_raw;
        int is64 = 1;
        for (int i = 1; i < 2048; i += 2)
            if (ii[i] != 0) { is64 = 0; break; }
        g_is64 = is64;
    }
    __syncthreads();
    for (int i = t; i < C2 * C2; i += 256)
        g_WsP[i] = g_avec[i >> 8] * Ws[i];
    for (int i = t; i < C2 * C_OUT; i += 256)
        g_WmP[i] = g_avec[i / C_OUT] * Wm[i];
    if (t < C_OUT) {
        float s = bm[t];
        for (int j = 0; j < C2; j++)
            s += g_cvec[j] * Wm[j * C_OUT + t];
        g_bmP[t] = s;
    }
}

__global__ __launch_bounds__(512) void idx_kernel(const void* __restrict__ nidx_raw)
{
    int i = blockIdx.x * 512 + threadIdx.x;
    if (i >= NK) return;
    if (g_is64) g_rows[i] = (int)((const long long*)nidx_raw)[i];
    else        g_rows[i] = ((const int*)nidx_raw)[i];
}

// ---------------------------------------------------------------------------
// 128x128 block-tile SGEMM, 256 threads, 8x8 microtile, BK=16.
// MODE 0: g_x = relu(features @ W1 + b1)          N=256 K=128
// MODE 1: out  = g_P @ g_WmP + g_bmP              N=128 K=256
// MODE 2: g_Y  = g_x @ g_WsP                      N=256 K=256 (no bias)
// ---------------------------------------------------------------------------
template<int MODE>
__global__ __launch_bounds__(256) void gemm128_kernel(
    const float* __restrict__ Ain, const float* __restrict__ Bin,
    const float* __restrict__ biasin, float* __restrict__ Cout, int M)
{
    constexpr int N = (MODE == 1) ? 128 : 256;
    constexpr int K = (MODE == 0) ? 128 : 256;
    const float* A = (MODE == 0) ? Ain : (MODE == 1 ? g_P : g_x);
    const float* B = (MODE == 0) ? Bin : (MODE == 1 ? g_WmP : g_WsP);
    float*       C = (MODE == 0) ? g_x : (MODE == 1 ? Cout : g_Y);

    __shared__ float AsT[16][132];
    __shared__ float Bs[16][128];

    int t  = threadIdx.x;
    int tx = t & 15, ty = t >> 4;
    int rowBase = blockIdx.x * 128;
    int colBase = blockIdx.y * 128;

    int ar = t >> 1, ac = (t & 1) << 3;             // A loader
    int grow = min(rowBase + ar, M - 1);            // clamp (values unused on OOB)
    const float* abase = A + (size_t)grow * K + ac;
    int br = t >> 4, bc = (t & 15) << 3;            // B loader
    const float* bbase = B + (size_t)br * N + colBase + bc;

    float acc[8][8] = {};

    for (int kb = 0; kb < K; kb += 16) {
        float4 a0 = *(const float4*)(abase + kb);
        float4 a1 = *(const float4*)(abase + kb + 4);
        AsT[ac + 0][ar] = a0.x; AsT[ac + 1][ar] = a0.y;
        AsT[ac + 2][ar] = a0.z; AsT[ac + 3][ar] = a0.w;
        AsT[ac + 4][ar] = a1.x; AsT[ac + 5][ar] = a1.y;
        AsT[ac + 6][ar] = a1.z; AsT[ac + 7][ar] = a1.w;
        float4 b0 = *(const float4*)(bbase + (size_t)kb * N);
        float4 b1 = *(const float4*)(bbase + (size_t)kb * N + 4);
        *(float4*)&Bs[br][bc]     = b0;
        *(float4*)&Bs[br][bc + 4] = b1;
        __syncthreads();
#pragma unroll
        for (int kk = 0; kk < 16; kk++) {
            float4 aA = *(float4*)&AsT[kk][ty << 2];
            float4 aB = *(float4*)&AsT[kk][64 + (ty << 2)];
            float4 bA = *(float4*)&Bs[kk][tx << 2];
            float4 bB = *(float4*)&Bs[kk][64 + (tx << 2)];
            float av[8] = {aA.x, aA.y, aA.z, aA.w, aB.x, aB.y, aB.z, aB.w};
            float bv[8] = {bA.x, bA.y, bA.z, bA.w, bB.x, bB.y, bB.z, bB.w};
#pragma unroll
            for (int i = 0; i < 8; i++)
#pragma unroll
                for (int j = 0; j < 8; j++)
                    acc[i][j] += av[i] * bv[j];
        }
        __syncthreads();
    }

    float4 bias0 = make_float4(0.f, 0.f, 0.f, 0.f);
    float4 bias1 = make_float4(0.f, 0.f, 0.f, 0.f);
    if (MODE == 0) {
        bias0 = *(const float4*)(biasin + colBase + (tx << 2));
        bias1 = *(const float4*)(biasin + colBase + 64 + (tx << 2));
    } else if (MODE == 1) {
        bias0 = *(const float4*)(g_bmP + colBase + (tx << 2));
        bias1 = *(const float4*)(g_bmP + colBase + 64 + (tx << 2));
    }

#pragma unroll
    for (int ih = 0; ih < 2; ih++)
#pragma unroll
        for (int i = 0; i < 4; i++) {
            int r = rowBase + ih * 64 + (ty << 2) + i;
            if (r < M) {
                float4 o0, o1;
                o0.x = acc[ih*4+i][0] + bias0.x; o0.y = acc[ih*4+i][1] + bias0.y;
                o0.z = acc[ih*4+i][2] + bias0.z; o0.w = acc[ih*4+i][3] + bias0.w;
                o1.x = acc[ih*4+i][4] + bias1.x; o1.y = acc[ih*4+i][5] + bias1.y;
                o1.z = acc[ih*4+i][6] + bias1.z; o1.w = acc[ih*4+i][7] + bias1.w;
                if (MODE == 0) {
                    o0.x = fmaxf(o0.x, 0.f); o0.y = fmaxf(o0.y, 0.f);
                    o0.z = fmaxf(o0.z, 0.f); o0.w = fmaxf(o0.w, 0.f);
                    o1.x = fmaxf(o1.x, 0.f); o1.y = fmaxf(o1.y, 0.f);
                    o1.z = fmaxf(o1.z, 0.f); o1.w = fmaxf(o1.w, 0.f);
                }
                *(float4*)(C + (size_t)r * N + colBase + (tx << 2))      = o0;
                *(float4*)(C + (size_t)r * N + colBase + 64 + (tx << 2)) = o1;
            }
        }
}

// ---------------------------------------------------------------------------
// pool: per (point, channel): softmax over k of Y[idx], weighted sum of x.
// 256 threads = 256 channels; APTS points per block. All loads coalesced
// (a warp reads 32 consecutive floats of one gathered row).
// ---------------------------------------------------------------------------
#define APTS 8

__global__ __launch_bounds__(256) void pool_kernel()
{
    __shared__ int rows[APTS * KNB];
    int t = threadIdx.x;
    int pbase = blockIdx.x * APTS;
    if (t < APTS * KNB) rows[t] = g_rows[pbase * KNB + t];
    __syncthreads();

    int c = t;
#pragma unroll 2
    for (int pi = 0; pi < APTS; pi++) {
        const int* rp = rows + pi * KNB;
        float v[KNB];
#pragma unroll
        for (int k = 0; k < KNB; k++)
            v[k] = g_Y[(size_t)rp[k] * C2 + c];
        float m = v[0];
#pragma unroll
        for (int k = 1; k < KNB; k++) m = fmaxf(m, v[k]);
        float sum = 0.f;
#pragma unroll
        for (int k = 0; k < KNB; k++) { v[k] = __expf(v[k] - m); sum += v[k]; }
        float p = 0.f;
#pragma unroll
        for (int k = 0; k < KNB; k++)
            p += v[k] * g_x[(size_t)rp[k] * C2 + c];
        g_P[(size_t)(pbase + pi) * C2 + c] = p * (1.0f / sum);
    }
}

// ---------------------------------------------------------------------------
extern "C" void kernel_launch(void* const* d_in, const int* in_sizes, int n_in,
                              void* d_out, int out_size)
{
    const float* features = (const float*)d_in[0];
    const void*  nidx     = d_in[1];
    const float* W1    = (const float*)d_in[2];
    const float* b1    = (const float*)d_in[3];
    const float* gamma = (const float*)d_in[4];
    const float* beta  = (const float*)d_in[5];
    const float* rmean = (const float*)d_in[6];
    const float* rvar  = (const float*)d_in[7];
    const float* Ws    = (const float*)d_in[8];
    const float* Wm    = (const float*)d_in[9];
    const float* bm    = (const float*)d_in[10];
    float* out = (float*)d_out;

    prep_kernel<<<1, 256>>>(gamma, beta, rmean, rvar, Ws, Wm, bm, nidx);
    idx_kernel<<<(NK + 511) / 512, 512>>>(nidx);

    int gx = (N_PTS + 127) / 128;   // 391
    gemm128_kernel<0><<<dim3(gx, C2 / 128), 256>>>(features, W1, b1, nullptr, N_PTS);
    gemm128_kernel<2><<<dim3(gx, C2 / 128), 256>>>(nullptr, nullptr, nullptr, nullptr, N_PTS);
    pool_kernel<<<N_PTS / APTS, 256>>>();
    gemm128_kernel<1><<<dim3(gx, C_OUT / 128), 256>>>(nullptr, nullptr, nullptr, out, N_PTS);
}